// round 10
// baseline (speedup 1.0000x reference)
#include <cuda_runtime.h>
#include <cuda_fp16.h>
#include <cstdint>

// Problem constants
#define CTXD   512
#define HIDD   2048
#define NCELLS 4096      // 64*64
#define NBATCH 8
#define KNN    8
#define MTOT   (NBATCH * NCELLS)   // 32768

// Scratch (allowed: __device__ globals)
__device__ __half g_aggh[(size_t)MTOT * CTXD];  // 32 MB fp16 agg
__device__ __half g_Wh[(size_t)HIDD * CTXD];    // 2 MB  fp16 W^T (N rows, K cols)

// ---------------------------------------------------------------------------
// Kernel 1: fused prep: agg (4 cells/block) + W transpose->fp16
// ---------------------------------------------------------------------------
__global__ __launch_bounds__(128) void prep_kernel(
    const float* __restrict__ x,
    const int*   __restrict__ nn_idx,
    const float* __restrict__ sim,
    const float* __restrict__ W)
{
    const int bid = blockIdx.x;
    const int t   = threadIdx.x;

    if (bid < 8192) {
        const int n0 = (bid & 1023) * 4;
        const int b  = bid >> 10;

        __shared__ int   s_idx[4 * KNN];
        __shared__ float s_sim[4 * KNN];
        if (t < 4 * KNN) {
            s_idx[t] = nn_idx[n0 * KNN + t];
            s_sim[t] = sim[n0 * KNN + t];
        }
        __syncthreads();

        const float4* xb = reinterpret_cast<const float4*>(x) +
                           (size_t)b * NCELLS * (CTXD / 4);
        uint2* dst = reinterpret_cast<uint2*>(g_aggh);

#pragma unroll
        for (int c = 0; c < 4; c++) {
            float4 acc = make_float4(0.f, 0.f, 0.f, 0.f);
#pragma unroll
            for (int k = 0; k < KNN; k++) {
                const float  s = s_sim[c * KNN + k];
                const float4 v = xb[(size_t)s_idx[c * KNN + k] * (CTXD / 4) + t];
                acc.x = fmaf(s, v.x, acc.x);
                acc.y = fmaf(s, v.y, acc.y);
                acc.z = fmaf(s, v.z, acc.z);
                acc.w = fmaf(s, v.w, acc.w);
            }
            __half2 h0 = __float22half2_rn(make_float2(acc.x, acc.y));
            __half2 h1 = __float22half2_rn(make_float2(acc.z, acc.w));
            uint2 p;
            p.x = *reinterpret_cast<uint32_t*>(&h0);
            p.y = *reinterpret_cast<uint32_t*>(&h1);
            dst[((size_t)b * NCELLS + n0 + c) * (CTXD / 4) + t] = p;
        }
    } else {
        const int wb = bid - 8192;
        const int bx = wb & 63;
        const int by = wb >> 6;
        const int tx = t & 31;
        const int ty = t >> 5;

        __shared__ float tile[32][33];
#pragma unroll
        for (int i = 0; i < 8; i++)
            tile[ty + i * 4][tx] =
                W[(size_t)(by * 32 + ty + i * 4) * HIDD + bx * 32 + tx];
        __syncthreads();
#pragma unroll
        for (int i = 0; i < 8; i++)
            g_Wh[(size_t)(bx * 32 + ty + i * 4) * CTXD + by * 32 + tx] =
                __float2half(tile[tx][ty + i * 4]);
    }
}

// ---------------------------------------------------------------------------
// Kernel 2: fp16 mma.sync GEMM, fp16 accumulators per K=64 chunk (rt 8),
// fp32 inter-chunk accumulation. 128x128 CTA tile, 8 warps (warp 32x64),
// BK=64, 3-stage cp.async, ldmatrix.
// ---------------------------------------------------------------------------
#define BM 128
#define BN 128
#define BK 64
#define NT (CTXD / BK)         // 8 k-chunks
#define SSTRIDE 72             // BK + 8 pad (halves)
#define TILE_H (128 * SSTRIDE)
#define STAGE_H (2 * TILE_H)
#define GEMM_SMEM (3 * STAGE_H * 2)   // 110592 bytes

__device__ __forceinline__ void cpasync16(uint32_t saddr, const void* g) {
    asm volatile("cp.async.cg.shared.global [%0], [%1], 16;\n" :: "r"(saddr), "l"(g));
}
__device__ __forceinline__ void ldsm_x4(uint32_t& r0, uint32_t& r1,
                                        uint32_t& r2, uint32_t& r3, uint32_t a) {
    asm volatile("ldmatrix.sync.aligned.m8n8.x4.shared.b16 {%0,%1,%2,%3},[%4];"
                 : "=r"(r0), "=r"(r1), "=r"(r2), "=r"(r3) : "r"(a));
}

__global__ __launch_bounds__(256, 1) void gemm_hmma(
    const __half* __restrict__ A,   // [MTOT][CTXD]
    const __half* __restrict__ B,   // [HIDD][CTXD]  (W^T)
    float*        __restrict__ C)   // [MTOT][HIDD]
{
    extern __shared__ __half sm[];

    const int tid  = threadIdx.x;
    const int lane = tid & 31;
    const int warp = tid >> 5;      // 0..7
    const int wm   = warp & 3;      // 32-row M quarter
    const int wn   = warp >> 2;     // 64-col N half
    const int g    = lane >> 2;
    const int t4   = lane & 3;

    const int m0 = blockIdx.y * BM;
    const int n0 = blockIdx.x * BN;

    float acc[2][8][4];             // fp32 inter-chunk accumulators
#pragma unroll
    for (int i = 0; i < 2; i++)
#pragma unroll
        for (int j = 0; j < 8; j++)
#pragma unroll
            for (int r = 0; r < 4; r++) acc[i][j][r] = 0.f;

    auto load_chunk = [&](int buf, int kt) {
        __half* Asb = sm + buf * STAGE_H;
        __half* Bsb = Asb + TILE_H;
        const __half* Ag = A + (size_t)m0 * CTXD + kt * BK;
        const __half* Bg = B + (size_t)n0 * CTXD + kt * BK;
#pragma unroll
        for (int i = 0; i < 4; i++) {
            int idx = i * 256 + tid;
            int row = idx >> 3;
            int c8  = (idx & 7) * 8;
            cpasync16((uint32_t)__cvta_generic_to_shared(Asb + row * SSTRIDE + c8),
                      Ag + (size_t)row * CTXD + c8);
        }
#pragma unroll
        for (int i = 0; i < 4; i++) {
            int idx = i * 256 + tid;
            int row = idx >> 3;
            int c8  = (idx & 7) * 8;
            cpasync16((uint32_t)__cvta_generic_to_shared(Bsb + row * SSTRIDE + c8),
                      Bg + (size_t)row * CTXD + c8);
        }
        asm volatile("cp.async.commit_group;\n");
    };

    load_chunk(0, 0);
    load_chunk(1, 1);

    const int a_r  = lane & 15;
    const int a_k  = (lane >> 4) * 8;
    const int b_r  = lane & 7;
    const int b_no = ((lane >> 3) >> 1) * 8;
    const int b_ko = ((lane >> 3) & 1) * 8;

    for (int kt = 0; kt < NT; ++kt) {
        if (kt + 1 < NT) asm volatile("cp.async.wait_group 1;\n");
        else             asm volatile("cp.async.wait_group 0;\n");
        __syncthreads();
        if (kt + 2 < NT) load_chunk((kt + 2) % 3, kt + 2);

        const __half* Asb = sm + (kt % 3) * STAGE_H;
        const __half* Bsb = Asb + TILE_H;

        // fp16 chunk accumulators (zeroed each chunk)
        uint32_t acch[2][8][2];
#pragma unroll
        for (int i = 0; i < 2; i++)
#pragma unroll
            for (int j = 0; j < 8; j++) {
                acch[i][j][0] = 0u;
                acch[i][j][1] = 0u;
            }

#pragma unroll
        for (int ks = 0; ks < 4; ++ks) {
            const int k0 = ks * 16;

            uint32_t af[2][4];
#pragma unroll
            for (int mi = 0; mi < 2; ++mi) {
                uint32_t a = (uint32_t)__cvta_generic_to_shared(
                    Asb + (wm * 32 + mi * 16 + a_r) * SSTRIDE + k0 + a_k);
                ldsm_x4(af[mi][0], af[mi][1], af[mi][2], af[mi][3], a);
            }
            uint32_t bf[8][2];
#pragma unroll
            for (int nj = 0; nj < 4; ++nj) {
                uint32_t a = (uint32_t)__cvta_generic_to_shared(
                    Bsb + (wn * 64 + nj * 16 + b_no + b_r) * SSTRIDE + k0 + b_ko);
                ldsm_x4(bf[2 * nj][0], bf[2 * nj][1],
                        bf[2 * nj + 1][0], bf[2 * nj + 1][1], a);
            }
#pragma unroll
            for (int mi = 0; mi < 2; ++mi)
#pragma unroll
                for (int ni = 0; ni < 8; ++ni) {
                    asm volatile(
                        "mma.sync.aligned.m16n8k16.row.col.f16.f16.f16.f16 "
                        "{%0,%1},{%2,%3,%4,%5},{%6,%7},{%0,%1};\n"
                        : "+r"(acch[mi][ni][0]), "+r"(acch[mi][ni][1])
                        : "r"(af[mi][0]), "r"(af[mi][1]),
                          "r"(af[mi][2]), "r"(af[mi][3]),
                          "r"(bf[ni][0]), "r"(bf[ni][1]));
                }
        }

        // convert chunk partials to fp32 and accumulate
#pragma unroll
        for (int mi = 0; mi < 2; ++mi)
#pragma unroll
            for (int ni = 0; ni < 8; ++ni) {
                float2 lo = __half22float2(
                    *reinterpret_cast<__half2*>(&acch[mi][ni][0]));
                float2 hi = __half22float2(
                    *reinterpret_cast<__half2*>(&acch[mi][ni][1]));
                acc[mi][ni][0] += lo.x;
                acc[mi][ni][1] += lo.y;
                acc[mi][ni][2] += hi.x;
                acc[mi][ni][3] += hi.y;
            }
        __syncthreads();
    }

    // epilogue
#pragma unroll
    for (int mi = 0; mi < 2; ++mi) {
#pragma unroll
        for (int ni = 0; ni < 8; ++ni) {
            const int r = m0 + wm * 32 + mi * 16 + g;
            const int c = n0 + wn * 64 + ni * 8 + t4 * 2;
            float2 v0 = make_float2(acc[mi][ni][0], acc[mi][ni][1]);
            float2 v1 = make_float2(acc[mi][ni][2], acc[mi][ni][3]);
            *reinterpret_cast<float2*>(C + (size_t)r * HIDD + c)       = v0;
            *reinterpret_cast<float2*>(C + (size_t)(r + 8) * HIDD + c) = v1;
        }
    }
}

// ---------------------------------------------------------------------------
extern "C" void kernel_launch(void* const* d_in, const int* in_sizes, int n_in,
                              void* d_out, int out_size) {
    const float* x      = (const float*)d_in[0];
    const float* W      = (const float*)d_in[1];
    const int*   nn_idx = (const int*)  d_in[2];
    const float* sim    = (const float*)d_in[3];
    float*       out    = (float*)d_out;

    __half* aggh = nullptr;
    __half* wh   = nullptr;
    cudaGetSymbolAddress((void**)&aggh, g_aggh);
    cudaGetSymbolAddress((void**)&wh,   g_Wh);

    cudaFuncSetAttribute(gemm_hmma,
                         cudaFuncAttributeMaxDynamicSharedMemorySize, GEMM_SMEM);

    prep_kernel<<<8192 + 1024, 128>>>(x, nn_idx, sim, W);

    dim3 g2(HIDD / BN, MTOT / BM);   // (16, 256)
    gemm_hmma<<<g2, 256, GEMM_SMEM>>>(aggh, wh, out);
}

// round 11
// speedup vs baseline: 1.1154x; 1.1154x over previous
#include <cuda_runtime.h>
#include <cuda_fp16.h>
#include <cstdint>

// Problem constants
#define CTXD   512
#define HIDD   2048
#define NCELLS 4096      // 64*64
#define NBATCH 8
#define KNN    8
#define MTOT   (NBATCH * NCELLS)   // 32768

// Scratch (allowed: __device__ globals)
__device__ __half g_aggh[(size_t)MTOT * CTXD];  // 32 MB fp16 agg
__device__ __half g_Wh[(size_t)HIDD * CTXD];    // 2 MB  fp16 W^T (N rows, K cols)

// ---------------------------------------------------------------------------
// Kernel 1: fused prep: agg (4 cells/block) + W transpose->fp16
// ---------------------------------------------------------------------------
__global__ __launch_bounds__(128) void prep_kernel(
    const float* __restrict__ x,
    const int*   __restrict__ nn_idx,
    const float* __restrict__ sim,
    const float* __restrict__ W)
{
    const int bid = blockIdx.x;
    const int t   = threadIdx.x;

    if (bid < 8192) {
        const int n0 = (bid & 1023) * 4;
        const int b  = bid >> 10;

        __shared__ int   s_idx[4 * KNN];
        __shared__ float s_sim[4 * KNN];
        if (t < 4 * KNN) {
            s_idx[t] = nn_idx[n0 * KNN + t];
            s_sim[t] = sim[n0 * KNN + t];
        }
        __syncthreads();

        const float4* xb = reinterpret_cast<const float4*>(x) +
                           (size_t)b * NCELLS * (CTXD / 4);
        uint2* dst = reinterpret_cast<uint2*>(g_aggh);

#pragma unroll
        for (int c = 0; c < 4; c++) {
            float4 acc = make_float4(0.f, 0.f, 0.f, 0.f);
#pragma unroll
            for (int k = 0; k < KNN; k++) {
                const float  s = s_sim[c * KNN + k];
                const float4 v = xb[(size_t)s_idx[c * KNN + k] * (CTXD / 4) + t];
                acc.x = fmaf(s, v.x, acc.x);
                acc.y = fmaf(s, v.y, acc.y);
                acc.z = fmaf(s, v.z, acc.z);
                acc.w = fmaf(s, v.w, acc.w);
            }
            __half2 h0 = __float22half2_rn(make_float2(acc.x, acc.y));
            __half2 h1 = __float22half2_rn(make_float2(acc.z, acc.w));
            uint2 p;
            p.x = *reinterpret_cast<uint32_t*>(&h0);
            p.y = *reinterpret_cast<uint32_t*>(&h1);
            dst[((size_t)b * NCELLS + n0 + c) * (CTXD / 4) + t] = p;
        }
    } else {
        const int wb = bid - 8192;
        const int bx = wb & 63;
        const int by = wb >> 6;
        const int tx = t & 31;
        const int ty = t >> 5;

        __shared__ float tile[32][33];
#pragma unroll
        for (int i = 0; i < 8; i++)
            tile[ty + i * 4][tx] =
                W[(size_t)(by * 32 + ty + i * 4) * HIDD + bx * 32 + tx];
        __syncthreads();
#pragma unroll
        for (int i = 0; i < 8; i++)
            g_Wh[(size_t)(bx * 32 + ty + i * 4) * CTXD + by * 32 + tx] =
                __float2half(tile[tx][ty + i * 4]);
    }
}

// ---------------------------------------------------------------------------
// Kernel 2: fp16 mma.sync GEMM. fp16 accumulation within each K=64 chunk,
// fp32 across chunks. 128x128 CTA tile, 16 warps (warp tile 32x32),
// 512 threads, BK=64, 3-stage cp.async, ldmatrix, 2 CTA/SM.
// ---------------------------------------------------------------------------
#define BM 128
#define BN 128
#define BK 64
#define NT (CTXD / BK)         // 8 k-chunks
#define SSTRIDE 72             // BK + 8 pad (halves)
#define TILE_H (128 * SSTRIDE)
#define STAGE_H (2 * TILE_H)
#define GEMM_SMEM (3 * STAGE_H * 2)   // 110592 bytes

__device__ __forceinline__ void cpasync16(uint32_t saddr, const void* g) {
    asm volatile("cp.async.cg.shared.global [%0], [%1], 16;\n" :: "r"(saddr), "l"(g));
}
__device__ __forceinline__ void ldsm_x4(uint32_t& r0, uint32_t& r1,
                                        uint32_t& r2, uint32_t& r3, uint32_t a) {
    asm volatile("ldmatrix.sync.aligned.m8n8.x4.shared.b16 {%0,%1,%2,%3},[%4];"
                 : "=r"(r0), "=r"(r1), "=r"(r2), "=r"(r3) : "r"(a));
}

__global__ __launch_bounds__(512, 2) void gemm_hmma(
    const __half* __restrict__ A,   // [MTOT][CTXD]
    const __half* __restrict__ B,   // [HIDD][CTXD]  (W^T)
    float*        __restrict__ C)   // [MTOT][HIDD]
{
    extern __shared__ __half sm[];

    const int tid  = threadIdx.x;
    const int lane = tid & 31;
    const int warp = tid >> 5;      // 0..15
    const int wm   = warp & 3;      // 32-row M quarter
    const int wn   = warp >> 2;     // 32-col N quarter
    const int g    = lane >> 2;
    const int t4   = lane & 3;

    const int m0 = blockIdx.y * BM;
    const int n0 = blockIdx.x * BN;

    float acc[2][4][4];             // fp32 inter-chunk accumulators (32 regs)
#pragma unroll
    for (int i = 0; i < 2; i++)
#pragma unroll
        for (int j = 0; j < 4; j++)
#pragma unroll
            for (int r = 0; r < 4; r++) acc[i][j][r] = 0.f;

    // loader: 512 threads, A/B: 1024 x 16B each -> 2+2 cp.async per thread
    auto load_chunk = [&](int buf, int kt) {
        __half* Asb = sm + buf * STAGE_H;
        __half* Bsb = Asb + TILE_H;
        const __half* Ag = A + (size_t)m0 * CTXD + kt * BK;
        const __half* Bg = B + (size_t)n0 * CTXD + kt * BK;
#pragma unroll
        for (int i = 0; i < 2; i++) {
            int idx = i * 512 + tid;
            int row = idx >> 3;
            int c8  = (idx & 7) * 8;
            cpasync16((uint32_t)__cvta_generic_to_shared(Asb + row * SSTRIDE + c8),
                      Ag + (size_t)row * CTXD + c8);
        }
#pragma unroll
        for (int i = 0; i < 2; i++) {
            int idx = i * 512 + tid;
            int row = idx >> 3;
            int c8  = (idx & 7) * 8;
            cpasync16((uint32_t)__cvta_generic_to_shared(Bsb + row * SSTRIDE + c8),
                      Bg + (size_t)row * CTXD + c8);
        }
        asm volatile("cp.async.commit_group;\n");
    };

    load_chunk(0, 0);
    load_chunk(1, 1);

    const int a_r  = lane & 15;
    const int a_k  = (lane >> 4) * 8;
    const int b_r  = lane & 7;
    const int b_no = ((lane >> 3) >> 1) * 8;
    const int b_ko = ((lane >> 3) & 1) * 8;

    for (int kt = 0; kt < NT; ++kt) {
        if (kt + 1 < NT) asm volatile("cp.async.wait_group 1;\n");
        else             asm volatile("cp.async.wait_group 0;\n");
        __syncthreads();
        if (kt + 2 < NT) load_chunk((kt + 2) % 3, kt + 2);

        const __half* Asb = sm + (kt % 3) * STAGE_H;
        const __half* Bsb = Asb + TILE_H;

        // fp16 chunk accumulators
        uint32_t acch[2][4][2];
#pragma unroll
        for (int i = 0; i < 2; i++)
#pragma unroll
            for (int j = 0; j < 4; j++) {
                acch[i][j][0] = 0u;
                acch[i][j][1] = 0u;
            }

#pragma unroll
        for (int ks = 0; ks < 4; ++ks) {
            const int k0 = ks * 16;

            uint32_t af[2][4];
#pragma unroll
            for (int mi = 0; mi < 2; ++mi) {
                uint32_t a = (uint32_t)__cvta_generic_to_shared(
                    Asb + (wm * 32 + mi * 16 + a_r) * SSTRIDE + k0 + a_k);
                ldsm_x4(af[mi][0], af[mi][1], af[mi][2], af[mi][3], a);
            }
            uint32_t bf[4][2];
#pragma unroll
            for (int nj = 0; nj < 2; ++nj) {
                uint32_t a = (uint32_t)__cvta_generic_to_shared(
                    Bsb + (wn * 32 + nj * 16 + b_no + b_r) * SSTRIDE + k0 + b_ko);
                ldsm_x4(bf[2 * nj][0], bf[2 * nj][1],
                        bf[2 * nj + 1][0], bf[2 * nj + 1][1], a);
            }
#pragma unroll
            for (int mi = 0; mi < 2; ++mi)
#pragma unroll
                for (int ni = 0; ni < 4; ++ni) {
                    asm volatile(
                        "mma.sync.aligned.m16n8k16.row.col.f16.f16.f16.f16 "
                        "{%0,%1},{%2,%3,%4,%5},{%6,%7},{%0,%1};\n"
                        : "+r"(acch[mi][ni][0]), "+r"(acch[mi][ni][1])
                        : "r"(af[mi][0]), "r"(af[mi][1]),
                          "r"(af[mi][2]), "r"(af[mi][3]),
                          "r"(bf[ni][0]), "r"(bf[ni][1]));
                }
        }

        // fold chunk partials into fp32
#pragma unroll
        for (int mi = 0; mi < 2; ++mi)
#pragma unroll
            for (int ni = 0; ni < 4; ++ni) {
                float2 lo = __half22float2(
                    *reinterpret_cast<__half2*>(&acch[mi][ni][0]));
                float2 hi = __half22float2(
                    *reinterpret_cast<__half2*>(&acch[mi][ni][1]));
                acc[mi][ni][0] += lo.x;
                acc[mi][ni][1] += lo.y;
                acc[mi][ni][2] += hi.x;
                acc[mi][ni][3] += hi.y;
            }
        __syncthreads();
    }

    // epilogue
#pragma unroll
    for (int mi = 0; mi < 2; ++mi) {
#pragma unroll
        for (int ni = 0; ni < 4; ++ni) {
            const int r = m0 + wm * 32 + mi * 16 + g;
            const int c = n0 + wn * 32 + ni * 8 + t4 * 2;
            float2 v0 = make_float2(acc[mi][ni][0], acc[mi][ni][1]);
            float2 v1 = make_float2(acc[mi][ni][2], acc[mi][ni][3]);
            *reinterpret_cast<float2*>(C + (size_t)r * HIDD + c)       = v0;
            *reinterpret_cast<float2*>(C + (size_t)(r + 8) * HIDD + c) = v1;
        }
    }
}

// ---------------------------------------------------------------------------
extern "C" void kernel_launch(void* const* d_in, const int* in_sizes, int n_in,
                              void* d_out, int out_size) {
    const float* x      = (const float*)d_in[0];
    const float* W      = (const float*)d_in[1];
    const int*   nn_idx = (const int*)  d_in[2];
    const float* sim    = (const float*)d_in[3];
    float*       out    = (float*)d_out;

    __half* aggh = nullptr;
    __half* wh   = nullptr;
    cudaGetSymbolAddress((void**)&aggh, g_aggh);
    cudaGetSymbolAddress((void**)&wh,   g_Wh);

    cudaFuncSetAttribute(gemm_hmma,
                         cudaFuncAttributeMaxDynamicSharedMemorySize, GEMM_SMEM);

    prep_kernel<<<8192 + 1024, 128>>>(x, nn_idx, sim, W);

    dim3 g2(HIDD / BN, MTOT / BM);   // (16, 256)
    gemm_hmma<<<g2, 512, GEMM_SMEM>>>(aggh, wh, out);
}

// round 12
// speedup vs baseline: 1.3460x; 1.2067x over previous
#include <cuda_runtime.h>
#include <cuda_fp16.h>
#include <cstdint>

// Problem constants
#define CTXD   512
#define HIDD   2048
#define NCELLS 4096      // 64*64
#define NBATCH 8
#define KNN    8
#define MTOT   (NBATCH * NCELLS)   // 32768

// Scratch (allowed: __device__ globals)
__device__ __half g_aggh[(size_t)MTOT * CTXD];  // 32 MB fp16 agg
__device__ __half g_Wh[(size_t)HIDD * CTXD];    // 2 MB  fp16 W^T
__device__ int    g_tile_ctr;                   // persistent-GEMM tile counter

// ---------------------------------------------------------------------------
// Kernel 1: fused prep. 256 threads.
//   blocks [0,2048):    agg over 4x4 cell tiles, 2 cells in flight
//   blocks [2048,3072): W transpose -> fp16
// ---------------------------------------------------------------------------
#define AGG_BLOCKS 2048
#define PREP_BLOCKS (AGG_BLOCKS + 1024)

__global__ __launch_bounds__(256) void prep_kernel(
    const float* __restrict__ x,
    const int*   __restrict__ nn_idx,
    const float* __restrict__ sim,
    const float* __restrict__ W)
{
    const int bid = blockIdx.x;
    const int t   = threadIdx.x;

    if (bid < AGG_BLOCKS) {
        const int b  = bid >> 8;            // batch
        const int tb = bid & 255;           // 16x16 grid of 4x4 tiles
        const int r0 = (tb >> 4) * 4;
        const int c0 = (tb & 15) * 4;

        __shared__ int   s_idx[16 * KNN];
        __shared__ float s_sim[16 * KNN];
        if (t < 128) {
            const int cell = t >> 3;
            const int k    = t & 7;
            const int n    = (r0 + (cell >> 2)) * 64 + c0 + (cell & 3);
            s_idx[t] = nn_idx[n * KNN + k];
            s_sim[t] = sim[n * KNN + k];
        }
        __syncthreads();

        const int lane = t & 127;           // float4 lane
        const int sub  = t >> 7;            // 0/1: which cell of the pair

        const float4* xb = reinterpret_cast<const float4*>(x) +
                           (size_t)b * NCELLS * (CTXD / 4);
        uint2* dst = reinterpret_cast<uint2*>(g_aggh);

#pragma unroll
        for (int round = 0; round < 8; round++) {
            const int ci = round * 2 + sub;                 // 0..15
            const int n  = (r0 + (ci >> 2)) * 64 + c0 + (ci & 3);
            float4 acc = make_float4(0.f, 0.f, 0.f, 0.f);
#pragma unroll
            for (int k = 0; k < KNN; k++) {
                const float  s = s_sim[ci * KNN + k];
                const float4 v = xb[(size_t)s_idx[ci * KNN + k] * (CTXD / 4) + lane];
                acc.x = fmaf(s, v.x, acc.x);
                acc.y = fmaf(s, v.y, acc.y);
                acc.z = fmaf(s, v.z, acc.z);
                acc.w = fmaf(s, v.w, acc.w);
            }
            __half2 h0 = __float22half2_rn(make_float2(acc.x, acc.y));
            __half2 h1 = __float22half2_rn(make_float2(acc.z, acc.w));
            uint2 p;
            p.x = *reinterpret_cast<uint32_t*>(&h0);
            p.y = *reinterpret_cast<uint32_t*>(&h1);
            dst[((size_t)b * NCELLS + n) * (CTXD / 4) + lane] = p;
        }
    } else {
        // wtrans: Wt[n][k] = (half)W[k][n], 32x32 tile, 256 threads
        const int wb = bid - AGG_BLOCKS;     // 0..1023
        const int bx = wb & 63;              // HIDD/32
        const int by = wb >> 6;              // CTXD/32
        const int tx = t & 31;
        const int ty = t >> 5;               // 0..7

        __shared__ float tile[32][33];
#pragma unroll
        for (int i = 0; i < 4; i++)
            tile[ty + i * 8][tx] =
                W[(size_t)(by * 32 + ty + i * 8) * HIDD + bx * 32 + tx];
        __syncthreads();
#pragma unroll
        for (int i = 0; i < 4; i++)
            g_Wh[(size_t)(bx * 32 + ty + i * 8) * CTXD + by * 32 + tx] =
                __float2half(tile[tx][ty + i * 8]);
    }
}

// ---------------------------------------------------------------------------
// Kernel 2: persistent fp16 mma.sync GEMM (R9 compute core).
// 128x128 tile, 8 warps (warp 32x64), BK=64, 3-stage cp.async with
// cross-tile prefetch, atomic tile scheduler, fp32 accum, 2 CTA/SM.
// ---------------------------------------------------------------------------
#define BM 128
#define BN 128
#define BK 64
#define NT (CTXD / BK)         // 8 k-chunks per tile
#define NTILES ((MTOT / BM) * (HIDD / BN))   // 4096
#define SSTRIDE 72             // BK + 8 pad (halves)
#define TILE_H (128 * SSTRIDE)
#define STAGE_H (2 * TILE_H)
#define GEMM_SMEM (3 * STAGE_H * 2)   // 110592 bytes
#define GEMM_CTAS 304

__device__ __forceinline__ void cpasync16(uint32_t saddr, const void* g) {
    asm volatile("cp.async.cg.shared.global [%0], [%1], 16;\n" :: "r"(saddr), "l"(g));
}
__device__ __forceinline__ void ldsm_x4(uint32_t& r0, uint32_t& r1,
                                        uint32_t& r2, uint32_t& r3, uint32_t a) {
    asm volatile("ldmatrix.sync.aligned.m8n8.x4.shared.b16 {%0,%1,%2,%3},[%4];"
                 : "=r"(r0), "=r"(r1), "=r"(r2), "=r"(r3) : "r"(a));
}

__global__ __launch_bounds__(256, 2) void gemm_hmma(
    const __half* __restrict__ A,   // [MTOT][CTXD]
    const __half* __restrict__ B,   // [HIDD][CTXD]  (W^T)
    float*        __restrict__ C)   // [MTOT][HIDD]
{
    extern __shared__ __half sm[];
    __shared__ int sm_next;

    const int tid  = threadIdx.x;
    const int lane = tid & 31;
    const int warp = tid >> 5;      // 0..7
    const int wm   = warp & 3;      // 32-row M quarter
    const int wn   = warp >> 2;     // 64-col N half
    const int g    = lane >> 2;
    const int t4   = lane & 3;

    // chunk loader: tile index + chunk kt -> stage buf
    auto load_chunk = [&](int buf, int tile, int kt) {
        const int m0 = (tile >> 4) * BM;
        const int n0 = (tile & 15) * BN;
        __half* Asb = sm + buf * STAGE_H;
        __half* Bsb = Asb + TILE_H;
        const __half* Ag = A + (size_t)m0 * CTXD + kt * BK;
        const __half* Bg = B + (size_t)n0 * CTXD + kt * BK;
#pragma unroll
        for (int i = 0; i < 4; i++) {
            int idx = i * 256 + tid;
            int row = idx >> 3;
            int c8  = (idx & 7) * 8;
            cpasync16((uint32_t)__cvta_generic_to_shared(Asb + row * SSTRIDE + c8),
                      Ag + (size_t)row * CTXD + c8);
        }
#pragma unroll
        for (int i = 0; i < 4; i++) {
            int idx = i * 256 + tid;
            int row = idx >> 3;
            int c8  = (idx & 7) * 8;
            cpasync16((uint32_t)__cvta_generic_to_shared(Bsb + row * SSTRIDE + c8),
                      Bg + (size_t)row * CTXD + c8);
        }
        asm volatile("cp.async.commit_group;\n");
    };

    // grab first tile
    if (tid == 0) sm_next = atomicAdd(&g_tile_ctr, 1);
    __syncthreads();
    int tile = sm_next;
    if (tile >= NTILES) return;

    load_chunk(0, tile, 0);
    load_chunk(1, tile, 1);
    int st = 0;        // stage of current compute chunk
    int ahead = 1;     // issued chunks beyond current

    const int a_r  = lane & 15;
    const int a_k  = (lane >> 4) * 8;
    const int b_r  = lane & 7;
    const int b_no = ((lane >> 3) >> 1) * 8;
    const int b_ko = ((lane >> 3) & 1) * 8;

    while (true) {
        float acc[2][8][4];
#pragma unroll
        for (int i = 0; i < 2; i++)
#pragma unroll
            for (int j = 0; j < 8; j++)
#pragma unroll
                for (int r = 0; r < 4; r++) acc[i][j][r] = 0.f;

        int next_tile = NTILES;

        for (int kt = 0; kt < NT; ++kt) {
            if (ahead > 0) asm volatile("cp.async.wait_group 1;\n");
            else           asm volatile("cp.async.wait_group 0;\n");
            __syncthreads();

            if (kt == NT - 3) {
                if (tid == 0) sm_next = atomicAdd(&g_tile_ctr, 1);
            }
            if (kt == NT - 2) next_tile = sm_next;   // sync at top of this iter
                                                      // ordered the kt==NT-3 write

            // prefetch chunk (current tile kt+2, or next tile's first chunks)
            if (kt + 2 < NT) {
                load_chunk((st + 2) % 3, tile, kt + 2);
                ahead = 2;
            } else if (next_tile < NTILES) {
                load_chunk((st + 2) % 3, next_tile, kt + 2 - NT);
                ahead = 2;
            }

            const __half* Asb = sm + st * STAGE_H;
            const __half* Bsb = Asb + TILE_H;

#pragma unroll
            for (int ks = 0; ks < 4; ++ks) {
                const int k0 = ks * 16;

                uint32_t af[2][4];
#pragma unroll
                for (int mi = 0; mi < 2; ++mi) {
                    uint32_t a = (uint32_t)__cvta_generic_to_shared(
                        Asb + (wm * 32 + mi * 16 + a_r) * SSTRIDE + k0 + a_k);
                    ldsm_x4(af[mi][0], af[mi][1], af[mi][2], af[mi][3], a);
                }
                uint32_t bf[8][2];
#pragma unroll
                for (int nj = 0; nj < 4; ++nj) {
                    uint32_t a = (uint32_t)__cvta_generic_to_shared(
                        Bsb + (wn * 64 + nj * 16 + b_no + b_r) * SSTRIDE + k0 + b_ko);
                    ldsm_x4(bf[2 * nj][0], bf[2 * nj][1],
                            bf[2 * nj + 1][0], bf[2 * nj + 1][1], a);
                }
#pragma unroll
                for (int mi = 0; mi < 2; ++mi)
#pragma unroll
                    for (int ni = 0; ni < 8; ++ni) {
                        asm volatile(
                            "mma.sync.aligned.m16n8k16.row.col.f32.f16.f16.f32 "
                            "{%0,%1,%2,%3},{%4,%5,%6,%7},{%8,%9},{%0,%1,%2,%3};\n"
                            : "+f"(acc[mi][ni][0]), "+f"(acc[mi][ni][1]),
                              "+f"(acc[mi][ni][2]), "+f"(acc[mi][ni][3])
                            : "r"(af[mi][0]), "r"(af[mi][1]),
                              "r"(af[mi][2]), "r"(af[mi][3]),
                              "r"(bf[ni][0]), "r"(bf[ni][1]));
                    }
            }
            __syncthreads();
            st = (st + 1) % 3;
            ahead -= 1;
        }

        // epilogue for this tile
        {
            const int m0 = (tile >> 4) * BM;
            const int n0 = (tile & 15) * BN;
#pragma unroll
            for (int mi = 0; mi < 2; ++mi) {
#pragma unroll
                for (int ni = 0; ni < 8; ++ni) {
                    const int r = m0 + wm * 32 + mi * 16 + g;
                    const int c = n0 + wn * 64 + ni * 8 + t4 * 2;
                    float2 v0 = make_float2(acc[mi][ni][0], acc[mi][ni][1]);
                    float2 v1 = make_float2(acc[mi][ni][2], acc[mi][ni][3]);
                    *reinterpret_cast<float2*>(C + (size_t)r * HIDD + c)       = v0;
                    *reinterpret_cast<float2*>(C + (size_t)(r + 8) * HIDD + c) = v1;
                }
            }
        }

        if (next_tile >= NTILES) break;
        tile = next_tile;
    }
}

// ---------------------------------------------------------------------------
extern "C" void kernel_launch(void* const* d_in, const int* in_sizes, int n_in,
                              void* d_out, int out_size) {
    const float* x      = (const float*)d_in[0];
    const float* W      = (const float*)d_in[1];
    const int*   nn_idx = (const int*)  d_in[2];
    const float* sim    = (const float*)d_in[3];
    float*       out    = (float*)d_out;

    __half* aggh = nullptr;
    __half* wh   = nullptr;
    int*    ctr  = nullptr;
    cudaGetSymbolAddress((void**)&aggh, g_aggh);
    cudaGetSymbolAddress((void**)&wh,   g_Wh);
    cudaGetSymbolAddress((void**)&ctr,  g_tile_ctr);

    cudaFuncSetAttribute(gemm_hmma,
                         cudaFuncAttributeMaxDynamicSharedMemorySize, GEMM_SMEM);

    cudaMemsetAsync(ctr, 0, sizeof(int));
    prep_kernel<<<PREP_BLOCKS, 256>>>(x, nn_idx, sim, W);
    gemm_hmma<<<GEMM_CTAS, 256, GEMM_SMEM>>>(aggh, wh, out);
}